// round 13
// baseline (speedup 1.0000x reference)
#include <cuda_runtime.h>
#include <cuda_fp16.h>
#include <cstdint>

// NTXentLoss fused, INT8 mma.sync (IMMA), persistent, phase-staggered edition.
// B=8192, D=128, G=16, T=0.5
//   prep:   2 row-pairs per warp (MLP 4): normalize, s8 quantize, exact diag.
//   main:   148 CTAs x 512 threads; 4096 units (64 rowtiles x 64 chunks of
//           128x128). 6-deep ring, sync every 2 units; odd warps process the
//           pair in REVERSE order so half the warps run MUFU epilogue while
//           the other half stream IMMA. Row sums accumulate in registers per
//           rowtile segment (<=2 per CTA), written once at the end.
//   final:  per-rowtile block gathers matching CTA segments + loss;
//           last-block ticket reduces 64 partials to the scalar.
// logit_log2 = dot_s32 * C, C = (2*log2e)/254^2; exp = exp2(logit_log2).

#define B_N 8192
#define D_K 128
#define NUNITS 4096                  // 64 rowtiles x 64 chunks
#define NCTAS 148
#define LOG2E 1.4426950408889634f
#define QS 254.0f                    // s8 quant scale on normalized components
#define CSCALE ((2.0f * LOG2E) / (QS * QS))
#define CHUNK_BYTES (128 * 128)      // 16 KB s8 B chunk
#define RING 6
#define SMEM_TOTAL (RING * CHUNK_BYTES)   // 96 KB ring

__device__ uint32_t g_a8[B_N * 32];   // zis s8x4, normalized * QS
__device__ uint32_t g_b8[B_N * 32];   // zjs s8x4, normalized * QS
__device__ float g_diag[B_N];         // exact fp32 cosine(zis_i, zjs_i)
__device__ float g_seg[NCTAS * 4 * 128]; // per-CTA segment row partials
__device__ float g_partial[64];
__device__ int g_done;                // last-block ticket (resets each run)

__device__ __forceinline__ uint32_t smem_u32(const void* p) {
    return (uint32_t)__cvta_generic_to_shared(p);
}
__device__ __forceinline__ float ex2f(float x) {
    float r;
    asm("ex2.approx.ftz.f32 %0, %1;" : "=f"(r) : "f"(x));
    return r;
}
__device__ __forceinline__ int q8(float x) {
    int q = __float2int_rn(x);
    return max(-127, min(127, q));
}
__device__ __forceinline__ uint32_t pack4(int q0, int q1, int q2, int q3) {
    return (uint32_t)(q0 & 0xFF) | ((uint32_t)(q1 & 0xFF) << 8)
         | ((uint32_t)(q2 & 0xFF) << 16) | ((uint32_t)q3 << 24);
}

// ---------------------------------------------------------------------------
// prep: one warp handles rows w and w+4096 (both matrices); all 4 float4
// loads issued before reductions (MLP 4); 6 shuffle chains interleave.
// ---------------------------------------------------------------------------
__global__ void __launch_bounds__(256) prep_kernel(const float* __restrict__ zis,
                                                   const float* __restrict__ zjs) {
    int w = (blockIdx.x * 256 + threadIdx.x) >> 5;   // 0..4095
    int lane = threadIdx.x & 31;
    int rA = w, rB = w + 4096;
    float4 viA = reinterpret_cast<const float4*>(zis)[rA * (D_K / 4) + lane];
    float4 vjA = reinterpret_cast<const float4*>(zjs)[rA * (D_K / 4) + lane];
    float4 viB = reinterpret_cast<const float4*>(zis)[rB * (D_K / 4) + lane];
    float4 vjB = reinterpret_cast<const float4*>(zjs)[rB * (D_K / 4) + lane];
    float aA = viA.x * viA.x + viA.y * viA.y + viA.z * viA.z + viA.w * viA.w;
    float bA = vjA.x * vjA.x + vjA.y * vjA.y + vjA.z * vjA.z + vjA.w * vjA.w;
    float dA = viA.x * vjA.x + viA.y * vjA.y + viA.z * vjA.z + viA.w * vjA.w;
    float aB = viB.x * viB.x + viB.y * viB.y + viB.z * viB.z + viB.w * viB.w;
    float bB = vjB.x * vjB.x + vjB.y * vjB.y + vjB.z * vjB.z + vjB.w * vjB.w;
    float dB = viB.x * vjB.x + viB.y * vjB.y + viB.z * vjB.z + viB.w * vjB.w;
#pragma unroll
    for (int o = 16; o; o >>= 1) {
        aA += __shfl_xor_sync(0xffffffffu, aA, o);
        bA += __shfl_xor_sync(0xffffffffu, bA, o);
        dA += __shfl_xor_sync(0xffffffffu, dA, o);
        aB += __shfl_xor_sync(0xffffffffu, aB, o);
        bB += __shfl_xor_sync(0xffffffffu, bB, o);
        dB += __shfl_xor_sync(0xffffffffu, dB, o);
    }
    float siA = rsqrtf(fmaxf(aA, 1e-24f)) * QS;
    float sjA = rsqrtf(fmaxf(bA, 1e-24f)) * QS;
    float siB = rsqrtf(fmaxf(aB, 1e-24f)) * QS;
    float sjB = rsqrtf(fmaxf(bB, 1e-24f)) * QS;
    g_a8[rA * 32 + lane] = pack4(q8(viA.x * siA), q8(viA.y * siA), q8(viA.z * siA), q8(viA.w * siA));
    g_b8[rA * 32 + lane] = pack4(q8(vjA.x * sjA), q8(vjA.y * sjA), q8(vjA.z * sjA), q8(vjA.w * sjA));
    g_a8[rB * 32 + lane] = pack4(q8(viB.x * siB), q8(viB.y * siB), q8(viB.z * siB), q8(viB.w * siB));
    g_b8[rB * 32 + lane] = pack4(q8(vjB.x * sjB), q8(vjB.y * sjB), q8(vjB.z * sjB), q8(vjB.w * sjB));
    if (lane == 0) {
        g_diag[rA] = dA / fmaxf(sqrtf(aA) * sqrtf(bA), 1e-8f);
        g_diag[rB] = dB / fmaxf(sqrtf(aB) * sqrtf(bB), 1e-8f);
    }
}

// ---------------------------------------------------------------------------
// stage one 128-col x 128-byte s8 B chunk. Row j = 8 x 16B; swizzle c^(j&7).
// ---------------------------------------------------------------------------
__device__ __forceinline__ void stage_chunk(uint32_t smbase, int colbase, int tid) {
#pragma unroll
    for (int i = 0; i < 2; i++) {
        int u = tid + i * 512;
        int j = u >> 3, c = u & 7;
        const void* src = (const char*)g_b8 + (colbase + j) * 128 + c * 16;
        uint32_t dst = smbase + (((j << 3) + (c ^ (j & 7))) << 4);
        asm volatile("cp.async.cg.shared.global [%0], [%1], 16;" :: "r"(dst), "l"(src));
    }
    asm volatile("cp.async.commit_group;");
}

// ---------------------------------------------------------------------------
// main: 148 persistent CTAs x 512 threads (16 warps, 4/SMSP).
// Unit u: rowtile rt = u>>6 (128 rows), chunk ch = u&63 (128 cols).
// Warp (wr, wc): wr=warp&7 -> 16 rows, wc=warp>>3 -> 64 of 128 chunk cols.
// Sync every 2 units; odd warps traverse the pair in reverse so MMA and
// epilogue phases interleave across warps on each SMSP.
// ---------------------------------------------------------------------------
__global__ void __launch_bounds__(512, 1) main_kernel() {
    extern __shared__ __align__(1024) unsigned char sm[];
    const uint32_t smb = smem_u32(sm);

    const int tid = threadIdx.x;
    const int lane = tid & 31;
    const int warp = tid >> 5;
    const int wr = warp & 7;
    const int wc = warp >> 3;
    const int g = lane >> 2;
    const int t4 = lane & 3;
    const int nb = wc * 64;
    const int rloc0 = wr * 16 + g;        // local row (0..127), +8 for second
    const int rev = warp & 1;             // odd warps reverse pair order

    const int lo = (int)(((long)blockIdx.x * NUNITS) / NCTAS);
    const int hi = (int)(((long)(blockIdx.x + 1) * NUNITS) / NCTAS);
    const int rt0cta = lo >> 6;           // first rowtile of this CTA (seg 0)

    // prologue: stage up to 4 chunks ahead
#pragma unroll
    for (int t = 0; t < 4; t++)
        if (lo + t < hi) stage_chunk(smb + ((lo + t) % RING) * CHUNK_BYTES,
                                     ((lo + t) & 63) * 128, tid);

    uint32_t aF[4][4];
    int cur_rt = -1;
    float segA[2] = {0.f, 0.f};           // rs0 per segment
    float segB[2] = {0.f, 0.f};           // rs1 per segment

    for (int u = lo; u < hi; u += 2) {
        const int umax = (u + 1 < hi) ? (u + 1) : u;
        const int pend = ((hi - 1 < u + 3) ? (hi - 1) : (u + 3)) - umax;
        if (pend <= 0)      asm volatile("cp.async.wait_group 0;");
        else if (pend == 1) asm volatile("cp.async.wait_group 1;");
        else                asm volatile("cp.async.wait_group 2;");
        __syncthreads();   // chunks u..umax visible; all warps past u-1

        if (u + 4 < hi)
            stage_chunk(smb + ((u + 4) % RING) * CHUNK_BYTES, ((u + 4) & 63) * 128, tid);
        if (u + 5 < hi)
            stage_chunk(smb + ((u + 5) % RING) * CHUNK_BYTES, ((u + 5) & 63) * 128, tid);

        for (int s = 0; s <= umax - u; s++) {
            const int v = rev ? (umax - s) : (u + s);
            const int rt = v >> 6;
            const int ch = v & 63;
            const int seg = (rt != rt0cta) ? 1 : 0;

            if (rt != cur_rt) {   // reload A fragments for new rowtile (L2-hot)
                cur_rt = rt;
                const int r0 = rt * 128 + rloc0, r1 = r0 + 8;
#pragma unroll
                for (int ks = 0; ks < 4; ks++) {
                    aF[ks][0] = g_a8[r0 * 32 + ks * 8 + t4];
                    aF[ks][1] = g_a8[r1 * 32 + ks * 8 + t4];
                    aF[ks][2] = g_a8[r0 * 32 + ks * 8 + 4 + t4];
                    aF[ks][3] = g_a8[r1 * 32 + ks * 8 + 4 + t4];
                }
            }

            const uint32_t base = smb + (v % RING) * CHUNK_BYTES;
            int acc[8][4];
#pragma unroll
            for (int f = 0; f < 8; f++)
#pragma unroll
                for (int e = 0; e < 4; e++) acc[f][e] = 0;

#pragma unroll
            for (int ks = 0; ks < 4; ks++) {
                uint32_t bF[8][2];
#pragma unroll
                for (int nf = 0; nf < 4; nf++) {
                    int j = nb + nf * 16 + ((lane >> 4) << 3) + (lane & 7);
                    int c = 2 * ks + ((lane >> 3) & 1);
                    uint32_t addr = base + (((j << 3) + (c ^ (j & 7))) << 4);
                    uint32_t r0, r1, r2, r3;
                    asm volatile("ldmatrix.sync.aligned.m8n8.x4.shared.b16 {%0,%1,%2,%3}, [%4];"
                                 : "=r"(r0), "=r"(r1), "=r"(r2), "=r"(r3) : "r"(addr));
                    bF[nf * 2][0] = r0;     bF[nf * 2][1] = r1;
                    bF[nf * 2 + 1][0] = r2; bF[nf * 2 + 1][1] = r3;
                }
#pragma unroll
                for (int f = 0; f < 8; f++) {
                    asm volatile(
                        "mma.sync.aligned.m16n8k32.row.col.s32.s8.s8.s32 "
                        "{%0,%1,%2,%3},{%4,%5,%6,%7},{%8,%9},{%0,%1,%2,%3};"
                        : "+r"(acc[f][0]), "+r"(acc[f][1]), "+r"(acc[f][2]), "+r"(acc[f][3])
                        : "r"(aF[ks][0]), "r"(aF[ks][1]), "r"(aF[ks][2]), "r"(aF[ks][3]),
                          "r"(bF[f][0]), "r"(bF[f][1]));
                }
            }

            float rs0 = 0.f, rs1 = 0.f;
            if (ch != rt) {
                // vector epilogue: s32 -> f32*C -> f16x2 ex2, half2 partial sums
                __half2 h0 = __float2half2_rn(0.f), h1 = h0;
#pragma unroll
                for (int f = 0; f < 8; f++) {
                    float a0 = (float)acc[f][0] * CSCALE, a1 = (float)acc[f][1] * CSCALE;
                    float a2v = (float)acc[f][2] * CSCALE, a3 = (float)acc[f][3] * CSCALE;
                    uint32_t p, q;
                    asm("cvt.rn.f16x2.f32 %0, %1, %2;" : "=r"(p) : "f"(a1), "f"(a0));
                    asm("ex2.approx.f16x2 %0, %0;" : "+r"(p));
                    h0 = __hadd2(h0, *reinterpret_cast<__half2*>(&p));
                    asm("cvt.rn.f16x2.f32 %0, %1, %2;" : "=r"(q) : "f"(a3), "f"(a2v));
                    asm("ex2.approx.f16x2 %0, %0;" : "+r"(q));
                    h1 = __hadd2(h1, *reinterpret_cast<__half2*>(&q));
                }
                float2 f0 = __half22float2(h0), f1 = __half22float2(h1);
                rs0 = f0.x + f0.y;
                rs1 = f1.x + f1.y;
            } else {
                // masked epilogue: rowtile == chunk -> local block test
#pragma unroll
                for (int f = 0; f < 8; f++) {
                    int c0 = nb + f * 8 + 2 * t4;
#pragma unroll
                    for (int e = 0; e < 4; e++) {
                        int rl = (e < 2) ? rloc0 : (rloc0 + 8);
                        int cl = c0 + (e & 1);
                        float ev = ex2f((float)acc[f][e] * CSCALE);
                        if ((rl >> 4) == (cl >> 4)) ev = 0.f;  // own block, diag incl.
                        if (e < 2) rs0 += ev; else rs1 += ev;
                    }
                }
            }
            segA[seg] += rs0;
            segB[seg] += rs1;
        }
    }

    // epilogue: quad-reduce both segments, one write per (warp, segment)
#pragma unroll
    for (int seg = 0; seg < 2; seg++) {
        float a = segA[seg], b = segB[seg];
        a += __shfl_xor_sync(0xffffffffu, a, 1);
        a += __shfl_xor_sync(0xffffffffu, a, 2);
        b += __shfl_xor_sync(0xffffffffu, b, 1);
        b += __shfl_xor_sync(0xffffffffu, b, 2);
        if (t4 == 0) {
            float* dst = &g_seg[(blockIdx.x * 4 + seg * 2 + wc) * 128];
            dst[rloc0] = a;
            dst[rloc0 + 8] = b;
        }
    }
}

// ---------------------------------------------------------------------------
// finalize: 64 CTAs (one per rowtile) x 128 threads; gathers the 2-4 CTA
// segments covering this rowtile, adds exact positive, computes loss,
// block-reduces; last block sums all 64 partials in fixed order.
// ---------------------------------------------------------------------------
__global__ void __launch_bounds__(128) finalize_kernel(float* __restrict__ out) {
    __shared__ float red[128];
    const int myrt = blockIdx.x;
    const int lr = threadIdx.x;
    float S = 0.f;
    for (int c = 0; c < NCTAS; c++) {
        int clo = (int)(((long)c * NUNITS) / NCTAS);
        int chi = (int)(((long)(c + 1) * NUNITS) / NCTAS);
        int rt0 = clo >> 6, rt1 = (chi - 1) >> 6;
        const float* segp = &g_seg[c * 4 * 128];
        if (rt0 == myrt)
            S += segp[lr] + segp[128 + lr];
        if (rt1 == myrt && rt1 != rt0)
            S += segp[2 * 128 + lr] + segp[3 * 128 + lr];
    }
    float d = g_diag[myrt * 128 + lr];
    float pos = 2.0f * d;             // sim / T
    S += ex2f(pos * LOG2E);           // add positive term
    red[lr] = logf(S) - pos;
    __syncthreads();
    for (int o = 64; o; o >>= 1) {
        if (lr < o) red[lr] += red[lr + o];
        __syncthreads();
    }
    if (lr == 0) {
        g_partial[myrt] = red[0];
        __threadfence();
        if (atomicAdd(&g_done, 1) == 63) {   // last block: deterministic sum
            float s = 0.f;
#pragma unroll
            for (int i = 0; i < 64; i++) s += g_partial[i];
            out[0] = s * (1.0f / (float)B_N);
            g_done = 0;                      // reset for next graph replay
        }
    }
}

extern "C" void kernel_launch(void* const* d_in, const int* in_sizes, int n_in,
                              void* d_out, int out_size) {
    (void)in_sizes; (void)n_in; (void)out_size;
    const float* zis = (const float*)d_in[0];
    const float* zjs = (const float*)d_in[1];
    cudaFuncSetAttribute(main_kernel, cudaFuncAttributeMaxDynamicSharedMemorySize,
                         SMEM_TOTAL);
    prep_kernel<<<512, 256>>>(zis, zjs);   // 4096 warps, 2 row-pairs each
    main_kernel<<<NCTAS, 512, SMEM_TOTAL>>>();
    finalize_kernel<<<64, 128>>>((float*)d_out);
}